// round 6
// baseline (speedup 1.0000x reference)
#include <cuda_runtime.h>
#include <cuda_bf16.h>
#include <math.h>

#define Bn    8
#define Hn    384
#define Wn    384
#define HW    (Hn*Wn)
#define NPIX  (Bn*HW)
#define NCLS  4
#define EDIM  8
#define NINST 33
#define RUNS_PER_IMG (HW/16)          // 9216
#define RUNS_X       (Wn/16)          // 24
#define SEG_BLK_PER_IMG 36
#define SEG_BLOCKS   (SEG_BLK_PER_IMG*Bn)       // 288
// ---- flat affinity stream: geo(B,16,HW) vs [gt_diff|gt_grid|gt_rgba] --------
#define F16   (16*HW/4)               // 589824 f4 per batch (geo)
#define F9    (9*HW/4)                // 331776
#define F3    (3*HW/4)                // 110592
#define F4q   (4*HW/4)                // 147456
#define AFF_F4_TOTAL (Bn*F16)         // 4718592
#define AFF_CHUNK 2048                // f4 per block (divides F9,F3,F4q)
#define AFF_BLOCKS (AFF_F4_TOTAL/AFF_CHUNK)     // 2304
#define SEMPX_BLOCKS (NPIX/4/256)               // 1152
#define HR_PER_IMG   (RUNS_PER_IMG*2)
#define K2_BLK_PER_IMG (HR_PER_IMG/256)         // 72
#define K2_BLOCKS    (K2_BLK_PER_IMG*Bn)        // 576
#define TOTAL_BLOCKS (SEG_BLOCKS + AFF_BLOCKS + SEMPX_BLOCKS + K2_BLOCKS + 1)
#define DONE_SEM_TARGET (AFF_BLOCKS + SEMPX_BLOCKS)

// ---------------- scratch ----------------------------------------------------
struct Scr {
    double sem, a9, a3, a4;
    float  cnt [Bn*NINST];
    float  ws  [Bn*NINST];
    float  ew  [Bn*NINST*EDIM];
    float  pull[Bn*NINST];
    int    done_seg, done_sem, done_k2;
};
__device__ Scr g_s;
__device__ unsigned int g_runinfo[Bn*RUNS_PER_IMG];   // mask16 | label<<16 | uni<<31

__device__ __forceinline__ float warp_redf(float v){
    #pragma unroll
    for (int o = 16; o > 0; o >>= 1) v += __shfl_down_sync(0xffffffffu, v, o);
    return v;
}

__device__ __forceinline__ float bweight(const int* __restrict__ L, int y, int x, int l)
{
    int ym = y > 0 ? y-1 : 0, yp = y < Hn-1 ? y+1 : Hn-1;
    int xm = x > 0 ? x-1 : 0, xp = x < Wn-1 ? x+1 : Wn-1;
    const int* r0 = L + ym*Wn;
    const int* r1 = L + y *Wn;
    const int* r2 = L + yp*Wn;
    bool bd = (r0[xm]!=l) | (r0[x]!=l) | (r0[xp]!=l)
            | (r1[xm]!=l) |              (r1[xp]!=l)
            | (r2[xm]!=l) | (r2[x]!=l) | (r2[xp]!=l);
    return bd ? 10.0f : 1.0f;
}

__device__ __forceinline__ void spin_until(int* ctr, int target)
{
    if (threadIdx.x == 0) {
        while (atomicAdd(ctr, 0) < target) __nanosleep(64);
        __threadfence();
    }
    __syncthreads();
}

__device__ __forceinline__ void signal_done(int* ctr)
{
    __syncthreads();
    if (threadIdx.x == 0) { __threadfence(); atomicAdd(ctr, 1); }
}

// block-reduce a float into a double global
__device__ __forceinline__ void block_acc(float v, double* dst)
{
    __shared__ float sh[8];
    int lane = threadIdx.x & 31, wid = threadIdx.x >> 5;
    v = warp_redf(v);
    if (lane == 0) sh[wid] = v;
    __syncthreads();
    if (wid == 0) {
        float x = lane < 8 ? sh[lane] : 0.f;
        x = warp_redf(x);
        if (lane == 0) atomicAdd(dst, (double)x);
    }
}

__device__ __forceinline__ float l1_4(const float4* __restrict__ g,
                                      const float4* __restrict__ t)
{
    float4 g0 = __ldcs(g),        g1 = __ldcs(g+256),
           g2 = __ldcs(g+512),    g3 = __ldcs(g+768);
    float4 t0 = __ldcs(t),        t1 = __ldcs(t+256),
           t2 = __ldcs(t+512),    t3 = __ldcs(t+768);
    float a = fabsf(g0.x-t0.x)+fabsf(g0.y-t0.y)+fabsf(g0.z-t0.z)+fabsf(g0.w-t0.w)
            + fabsf(g1.x-t1.x)+fabsf(g1.y-t1.y)+fabsf(g1.z-t1.z)+fabsf(g1.w-t1.w)
            + fabsf(g2.x-t2.x)+fabsf(g2.y-t2.y)+fabsf(g2.z-t2.z)+fabsf(g2.w-t2.w)
            + fabsf(g3.x-t3.x)+fabsf(g3.y-t3.y)+fabsf(g3.z-t3.z)+fabsf(g3.w-t3.w);
    return a;
}

// =============================================================================
__global__ void __launch_bounds__(256, 5)
K(const float* __restrict__ sem, const int* __restrict__ cl,
  const float* __restrict__ geo, const float* __restrict__ gd,
  const float* __restrict__ gg,  const float* __restrict__ gr,
  const int*   __restrict__ lbl, const float* __restrict__ emb,
  float* __restrict__ out, int out_size)
{
    int bid = blockIdx.x;

    // ======================= SEG =============================================
    if (bid < SEG_BLOCKS) {
        int b   = bid / SEG_BLK_PER_IMG;
        int blk = bid - b*SEG_BLK_PER_IMG;

        __shared__ float s_cnt[NINST], s_ws[NINST], s_ew[NINST*EDIM];
        for (int i = threadIdx.x; i < NINST; i += blockDim.x) { s_cnt[i]=0.f; s_ws[i]=0.f; }
        for (int i = threadIdx.x; i < NINST*EDIM; i += blockDim.x) s_ew[i]=0.f;
        __syncthreads();

        const int*   L = lbl + b*HW;
        const float* E = emb + (size_t)b*EDIM*HW;

        int r = blk*blockDim.x + threadIdx.x;
        int y  = r / RUNS_X;
        int x0 = (r - y*RUNS_X) * 16;
        int base = y*Wn + x0;

        const int*  rM = L + base;
        const int4* m4 = (const int4*)rM;
        int4 a0 = m4[0], a1 = m4[1], a2 = m4[2], a3 = m4[3];
        int l = a0.x;
        bool uni = (a0.y==l)&(a0.z==l)&(a0.w==l)
                 & (a1.x==l)&(a1.y==l)&(a1.z==l)&(a1.w==l)
                 & (a2.x==l)&(a2.y==l)&(a2.z==l)&(a2.w==l)
                 & (a3.x==l)&(a3.y==l)&(a3.z==l)&(a3.w==l);

        if (uni) {
            int ym = y > 0 ? y-1 : 0, yp = y < Hn-1 ? y+1 : Hn-1;
            const int* rT = L + ym*Wn + x0;
            const int* rB = L + yp*Wn + x0;
            const int4* t4 = (const int4*)rT;
            const int4* b4 = (const int4*)rB;
            unsigned int bad = 0;
            #pragma unroll
            for (int k = 0; k < 4; k++) {
                int4 tt = t4[k];
                bad |= ((unsigned)(tt.x!=l)<<(1+4*k)) | ((unsigned)(tt.y!=l)<<(2+4*k))
                     | ((unsigned)(tt.z!=l)<<(3+4*k)) | ((unsigned)(tt.w!=l)<<(4+4*k));
                int4 bb = b4[k];
                bad |= ((unsigned)(bb.x!=l)<<(1+4*k)) | ((unsigned)(bb.y!=l)<<(2+4*k))
                     | ((unsigned)(bb.z!=l)<<(3+4*k)) | ((unsigned)(bb.w!=l)<<(4+4*k));
            }
            int xl = (x0 > 0) ? -1 : 0;
            int xr = (x0+16 < Wn) ? 16 : 15;
            bad |= (unsigned)(rT[xl]!=l) | ((unsigned)(rT[xr]!=l)<<17);
            bad |= (unsigned)(rB[xl]!=l) | ((unsigned)(rB[xr]!=l)<<17);
            bad |= (unsigned)(rM[xl]!=l) | ((unsigned)(rM[xr]!=l)<<17);

            unsigned int mask = (bad | (bad>>1) | (bad>>2)) & 0xFFFFu;

            atomicAdd(&s_cnt[l], 16.0f);
            atomicAdd(&s_ws [l], 16.0f + 9.0f*(float)__popc(mask));
            #pragma unroll
            for (int c = 0; c < EDIM; c++) {
                const float4* Ep = (const float4*)(E + (size_t)c*HW + base);
                float4 e0 = Ep[0], e1 = Ep[1], e2 = Ep[2], e3 = Ep[3];
                float ev[16] = {e0.x,e0.y,e0.z,e0.w, e1.x,e1.y,e1.z,e1.w,
                                e2.x,e2.y,e2.z,e2.w, e3.x,e3.y,e3.z,e3.w};
                float acc = 0.f;
                #pragma unroll
                for (int i = 0; i < 16; i++)
                    acc += ev[i] * fmaf((float)((mask>>i)&1u), 9.0f, 1.0f);
                atomicAdd(&s_ew[l*EDIM+c], acc);
            }
            g_runinfo[b*RUNS_PER_IMG + r] = mask | ((unsigned)l<<16) | (1u<<31);
        } else {
            int ls[16] = {a0.x,a0.y,a0.z,a0.w, a1.x,a1.y,a1.z,a1.w,
                          a2.x,a2.y,a2.z,a2.w, a3.x,a3.y,a3.z,a3.w};
            unsigned int mask = 0;
            #pragma unroll 1
            for (int i = 0; i < 16; i++) {
                int li = ls[i];
                float w = bweight(L, y, x0+i, li);
                if (w > 1.f) mask |= (1u<<i);
                atomicAdd(&s_cnt[li], 1.0f);
                atomicAdd(&s_ws [li], w);
                for (int c = 0; c < EDIM; c++)
                    atomicAdd(&s_ew[li*EDIM+c], E[(size_t)c*HW + base + i] * w);
            }
            g_runinfo[b*RUNS_PER_IMG + r] = mask;
        }
        __syncthreads();
        for (int i = threadIdx.x; i < NINST; i += blockDim.x) {
            if (s_cnt[i] != 0.f) atomicAdd(&g_s.cnt[b*NINST+i], s_cnt[i]);
            if (s_ws [i] != 0.f) atomicAdd(&g_s.ws [b*NINST+i], s_ws [i]);
        }
        for (int i = threadIdx.x; i < NINST*EDIM; i += blockDim.x)
            if (s_ew[i] != 0.f) atomicAdd(&g_s.ew[b*NINST*EDIM+i], s_ew[i]);

        signal_done(&g_s.done_seg);
        return;
    }
    bid -= SEG_BLOCKS;

    // ======================= AFF (flat L1 stream) ============================
    if (bid < AFF_BLOCKS) {
        long c0 = (long)bid * AFF_CHUNK;          // f4 index into geo
        int  b  = (int)(c0 / F16);
        long k0 = c0 - (long)b*F16;               // f4 offset within batch's 16HW

        const float4* gsrc = (const float4*)geo + c0 + threadIdx.x;
        const float4* tsrc;
        double* dst;
        if (k0 < F9) {
            tsrc = (const float4*)gd + (long)b*F9 + k0;
            dst = &g_s.a9;
        } else if (k0 < F9 + F3) {
            tsrc = (const float4*)gg + (long)b*F3 + (k0 - F9);
            dst = &g_s.a3;
        } else {
            tsrc = (const float4*)gr + (long)b*F4q + (k0 - F9 - F3);
            dst = &g_s.a4;
        }
        tsrc += threadIdx.x;

        float acc = l1_4(gsrc, tsrc) + l1_4(gsrc + 1024, tsrc + 1024);
        block_acc(acc, dst);
        signal_done(&g_s.done_sem);
        return;
    }
    bid -= AFF_BLOCKS;

    // ======================= SEMPX (log-softmax NLL) =========================
    if (bid < SEMPX_BLOCKS) {
        int t  = bid*blockDim.x + threadIdx.x;
        int H4 = HW/4;
        int b  = t / H4;
        int q4 = t - b*H4;
        size_t q = (size_t)q4 * 4;

        const float4* s4 = (const float4*)(sem + (size_t)b*NCLS*HW + q);
        float4 x0 = __ldcs(s4);
        float4 x1 = __ldcs(s4 + HW/4);
        float4 x2 = __ldcs(s4 + 2*(HW/4));
        float4 x3 = __ldcs(s4 + 3*(HW/4));
        int4 cc = __ldcs((const int4*)(cl + (size_t)b*HW + q));

        float s = 0.f;
        {
            float a[4][4] = {{x0.x,x1.x,x2.x,x3.x},{x0.y,x1.y,x2.y,x3.y},
                             {x0.z,x1.z,x2.z,x3.z},{x0.w,x1.w,x2.w,x3.w}};
            int   ci[4] = {cc.x, cc.y, cc.z, cc.w};
            #pragma unroll
            for (int j = 0; j < 4; j++) {
                float m = fmaxf(fmaxf(a[j][0],a[j][1]), fmaxf(a[j][2],a[j][3]));
                float sum = __expf(a[j][0]-m)+__expf(a[j][1]-m)
                          + __expf(a[j][2]-m)+__expf(a[j][3]-m);
                float lse = m + __logf(sum);
                int c = ci[j];
                float xc = (c==0) ? a[j][0] : ((c==1) ? a[j][1] : ((c==2) ? a[j][2] : a[j][3]));
                s += lse - xc;
            }
        }
        block_acc(s, &g_s.sem);
        signal_done(&g_s.done_sem);
        return;
    }
    bid -= SEMPX_BLOCKS;

    // ======================= PULL (waits on seg) =============================
    if (bid < K2_BLOCKS) {
        spin_until(&g_s.done_seg, SEG_BLOCKS);

        int b   = bid / K2_BLK_PER_IMG;
        int blk = bid - b*K2_BLK_PER_IMG;

        __shared__ float s_ctr[NINST*EDIM];
        __shared__ float s_pull[NINST];
        for (int i = threadIdx.x; i < NINST*EDIM; i += blockDim.x)
            s_ctr[i] = g_s.ew[b*NINST*EDIM + i] / (g_s.ws[b*NINST + (i>>3)] + 1e-8f);
        for (int i = threadIdx.x; i < NINST; i += blockDim.x) s_pull[i] = 0.f;
        __syncthreads();

        const float* E = emb + (size_t)b*EDIM*HW;

        int r8 = blk*blockDim.x + threadIdx.x;
        int y  = r8 / (2*RUNS_X);
        int x8 = (r8 - y*(2*RUNS_X)) * 8;
        int base = y*Wn + x8;

        unsigned int info = g_runinfo[b*RUNS_PER_IMG + y*RUNS_X + (x8>>4)];
        unsigned int mask8 = (info >> (((x8>>3)&1)*8)) & 0xFFu;

        if (info & (1u<<31)) {
            int l = (int)((info>>16) & 0x3Fu);
            float ss[8];
            #pragma unroll
            for (int i = 0; i < 8; i++) ss[i] = 0.f;
            #pragma unroll
            for (int c = 0; c < EDIM; c++) {
                float ccv = s_ctr[l*EDIM+c];
                const float4* Ep = (const float4*)(E + (size_t)c*HW + base);
                float4 e0 = Ep[0], e1 = Ep[1];
                float d0=e0.x-ccv, d1=e0.y-ccv, d2=e0.z-ccv, d3=e0.w-ccv;
                float d4=e1.x-ccv, d5=e1.y-ccv, d6=e1.z-ccv, d7=e1.w-ccv;
                ss[0]+=d0*d0; ss[1]+=d1*d1; ss[2]+=d2*d2; ss[3]+=d3*d3;
                ss[4]+=d4*d4; ss[5]+=d5*d5; ss[6]+=d6*d6; ss[7]+=d7*d7;
            }
            float acc = 0.f;
            #pragma unroll
            for (int i = 0; i < 8; i++) {
                float dist = sqrtf(fmaxf(ss[i], 1e-12f));
                float t = fmaxf(dist - 0.5f, 0.f);
                float w = fmaf((float)((mask8>>i)&1u), 9.0f, 1.0f);
                acc += t*t*w;
            }
            atomicAdd(&s_pull[l], acc);
        } else {
            const int* Lp = lbl + b*HW + base;
            int4 L0 = ((const int4*)Lp)[0];
            int4 L1 = ((const int4*)Lp)[1];
            int ls[8] = {L0.x,L0.y,L0.z,L0.w, L1.x,L1.y,L1.z,L1.w};
            #pragma unroll 1
            for (int i = 0; i < 8; i++) {
                int l = ls[i];
                float ssv = 0.f;
                for (int c = 0; c < EDIM; c++) {
                    float d = E[(size_t)c*HW + base + i] - s_ctr[l*EDIM+c];
                    ssv += d*d;
                }
                float dist = sqrtf(fmaxf(ssv, 1e-12f));
                float t = fmaxf(dist - 0.5f, 0.f);
                float w = fmaf((float)((mask8>>i)&1u), 9.0f, 1.0f);
                atomicAdd(&s_pull[l], t*t*w);
            }
        }
        __syncthreads();
        for (int i = threadIdx.x; i < NINST; i += blockDim.x)
            if (s_pull[i] != 0.f) atomicAdd(&g_s.pull[b*NINST+i], s_pull[i]);

        signal_done(&g_s.done_k2);
        return;
    }

    // ======================= FINALIZE ========================================
    spin_until(&g_s.done_sem, DONE_SEM_TARGET);
    spin_until(&g_s.done_k2,  K2_BLOCKS);

    __shared__ float s_ctr[Bn][NINST*EDIM];
    __shared__ float s_cnt[Bn][NINST];
    __shared__ float rp[Bn], rq[Bn], rn[Bn];
    __shared__ int   rpres[Bn];

    for (int i = threadIdx.x; i < Bn*NINST*EDIM; i += blockDim.x) {
        int b = i / (NINST*EDIM), k = i % (NINST*EDIM);
        s_ctr[b][k] = g_s.ew[i] / (g_s.ws[b*NINST + (k>>3)] + 1e-8f);
    }
    for (int i = threadIdx.x; i < Bn*NINST; i += blockDim.x)
        s_cnt[i/NINST][i%NINST] = g_s.cnt[i];
    __syncthreads();

    int wid = threadIdx.x >> 5, lane = threadIdx.x & 31;
    if (wid < Bn) {
        int b = wid;
        float pull = 0, norm = 0; int np = 0;
        for (int k = lane; k < NINST; k += 32) {
            bool pres = (k > 0) && (s_cnt[b][k] > 0.f);
            if (pres) {
                pull += g_s.pull[b*NINST+k] / fmaxf(s_cnt[b][k], 1.0f);
                float ssn = 0;
                #pragma unroll
                for (int c = 0; c < EDIM; c++) { float v = s_ctr[b][k*EDIM+c]; ssn += v*v; }
                norm += sqrtf(fmaxf(ssn, 1e-12f));
                np++;
            }
        }
        float push = 0; int npair = 0;
        for (int idx = lane; idx < NINST*NINST; idx += 32) {
            int i = idx / NINST, j = idx % NINST;
            if (j > i && i > 0 && s_cnt[b][i] > 0.f && s_cnt[b][j] > 0.f) {
                float ssd = 0;
                #pragma unroll
                for (int c = 0; c < EDIM; c++) {
                    float d = s_ctr[b][i*EDIM+c] - s_ctr[b][j*EDIM+c];
                    ssd += d*d;
                }
                float pd = sqrtf(fmaxf(ssd, 1e-12f));
                float t = fmaxf(3.0f - pd, 0.f);
                push += t*t; npair++;
            }
        }
        pull = warp_redf(pull); norm = warp_redf(norm); push = warp_redf(push);
        np   = __reduce_add_sync(0xffffffffu, np);
        npair= __reduce_add_sync(0xffffffffu, npair);
        if (lane == 0) {
            rp[b] = pull;
            rq[b] = push / fmaxf((float)npair, 1.0f);
            rn[b] = norm / fmaxf((float)np, 1.0f);
            rpres[b] = (np > 0) ? 1 : 0;
        }
    }
    __syncthreads();
    if (threadIdx.x == 0) {
        float pull = 0, push = 0, norm = 0; int n = 0;
        for (int bb = 0; bb < Bn; bb++) { pull += rp[bb]; push += rq[bb]; norm += rn[bb]; n += rpres[bb]; }
        float nn  = fmaxf((float)n, 1.0f);
        float ins = (pull + push + 0.001f*norm) / nn;
        float semv = (float)(g_s.sem / (double)NPIX);
        float aff  = (float)(g_s.a9/(double)((size_t)Bn*9*HW)
                           + g_s.a3/(double)((size_t)Bn*3*HW)
                           + g_s.a4/(double)((size_t)Bn*4*HW));
        out[0] = semv + aff + ins;
        if (out_size > 1) out[1] = semv;
        if (out_size > 2) out[2] = aff;
        if (out_size > 3) out[3] = ins;
    }
}

// ---------------- entry -------------------------------------------------------
extern "C" void kernel_launch(void* const* d_in, const int* in_sizes, int n_in,
                              void* d_out, int out_size)
{
    const float* sem  = (const float*)d_in[0];
    const int*   cl   = (const int*)  d_in[1];
    const float* inst = (const float*)d_in[2];
    const float* geo  = (const float*)d_in[3];
    const float* gd   = (const float*)d_in[4];
    const float* gg   = (const float*)d_in[5];
    const float* gr   = (const float*)d_in[6];
    const int*   lbl  = (const int*)  d_in[7];
    float* out = (float*)d_out;

    void* scr = nullptr;
    cudaGetSymbolAddress(&scr, g_s);
    cudaMemsetAsync(scr, 0, sizeof(Scr));

    K<<<TOTAL_BLOCKS, 256>>>(sem, cl, geo, gd, gg, gr, lbl, inst, out, out_size);
}

// round 7
// speedup vs baseline: 1.0048x; 1.0048x over previous
#include <cuda_runtime.h>
#include <cuda_bf16.h>
#include <math.h>

#define Bn    8
#define Hn    384
#define Wn    384
#define HW    (Hn*Wn)
#define NPIX  (Bn*HW)
#define NCLS  4
#define EDIM  8
#define NINST 33
#define RUNS_PER_IMG (HW/16)          // 9216
#define RUNS_X       (Wn/16)          // 24
#define SEG_BLK_PER_IMG 36
#define SEG_BLOCKS   (SEG_BLK_PER_IMG*Bn)       // 288
// ---- flat affinity stream: geo(B,16,HW) vs [gt_diff|gt_grid|gt_rgba] --------
#define F16   (16*HW/4)               // 589824 f4 per batch (geo)
#define F9    (9*HW/4)                // 331776
#define F3    (3*HW/4)                // 110592
#define F4q   (4*HW/4)                // 147456
#define AFF_F4_TOTAL (Bn*F16)         // 4718592
#define AFF_CHUNK 2048                // f4 per block (divides F9,F3,F4q)
#define AFF_BLOCKS (AFF_F4_TOTAL/AFF_CHUNK)     // 2304
#define SEMPX_BLOCKS (NPIX/4/256)               // 1152
#define HR_PER_IMG   (RUNS_PER_IMG*2)
#define K2_BLK_PER_IMG (HR_PER_IMG/256)         // 72
#define K2_BLOCKS    (K2_BLK_PER_IMG*Bn)        // 576
#define TOTAL_BLOCKS (SEG_BLOCKS + AFF_BLOCKS + SEMPX_BLOCKS + K2_BLOCKS + 1)
#define DONE_SEM_TARGET (AFF_BLOCKS + SEMPX_BLOCKS)

// ---------------- scratch ----------------------------------------------------
struct Scr {
    double sem, a9, a3, a4;
    float  cnt [Bn*NINST];
    float  ws  [Bn*NINST];
    float  ew  [Bn*NINST*EDIM];
    float  pull[Bn*NINST];
    int    done_seg, done_sem, done_k2;
};
__device__ Scr g_s;
__device__ unsigned int g_runinfo[Bn*RUNS_PER_IMG];   // mask16 | label<<16 | uni<<31

__device__ __forceinline__ float warp_redf(float v){
    #pragma unroll
    for (int o = 16; o > 0; o >>= 1) v += __shfl_down_sync(0xffffffffu, v, o);
    return v;
}

__device__ __forceinline__ float bweight(const int* __restrict__ L, int y, int x, int l)
{
    int ym = y > 0 ? y-1 : 0, yp = y < Hn-1 ? y+1 : Hn-1;
    int xm = x > 0 ? x-1 : 0, xp = x < Wn-1 ? x+1 : Wn-1;
    const int* r0 = L + ym*Wn;
    const int* r1 = L + y *Wn;
    const int* r2 = L + yp*Wn;
    bool bd = (r0[xm]!=l) | (r0[x]!=l) | (r0[xp]!=l)
            | (r1[xm]!=l) |              (r1[xp]!=l)
            | (r2[xm]!=l) | (r2[x]!=l) | (r2[xp]!=l);
    return bd ? 10.0f : 1.0f;
}

__device__ __forceinline__ void spin_until(int* ctr, int target)
{
    if (threadIdx.x == 0) {
        while (atomicAdd(ctr, 0) < target) __nanosleep(64);
        __threadfence();
    }
    __syncthreads();
}

__device__ __forceinline__ void signal_done(int* ctr)
{
    __syncthreads();
    if (threadIdx.x == 0) { __threadfence(); atomicAdd(ctr, 1); }
}

// block-reduce a float into a double global
__device__ __forceinline__ void block_acc(float v, double* dst)
{
    __shared__ float sh[8];
    int lane = threadIdx.x & 31, wid = threadIdx.x >> 5;
    v = warp_redf(v);
    if (lane == 0) sh[wid] = v;
    __syncthreads();
    if (wid == 0) {
        float x = lane < 8 ? sh[lane] : 0.f;
        x = warp_redf(x);
        if (lane == 0) atomicAdd(dst, (double)x);
    }
}

__device__ __forceinline__ float l1_4(const float4* __restrict__ g,
                                      const float4* __restrict__ t)
{
    float4 g0 = __ldcs(g),        g1 = __ldcs(g+256),
           g2 = __ldcs(g+512),    g3 = __ldcs(g+768);
    float4 t0 = __ldcs(t),        t1 = __ldcs(t+256),
           t2 = __ldcs(t+512),    t3 = __ldcs(t+768);
    float a = fabsf(g0.x-t0.x)+fabsf(g0.y-t0.y)+fabsf(g0.z-t0.z)+fabsf(g0.w-t0.w)
            + fabsf(g1.x-t1.x)+fabsf(g1.y-t1.y)+fabsf(g1.z-t1.z)+fabsf(g1.w-t1.w)
            + fabsf(g2.x-t2.x)+fabsf(g2.y-t2.y)+fabsf(g2.z-t2.z)+fabsf(g2.w-t2.w)
            + fabsf(g3.x-t3.x)+fabsf(g3.y-t3.y)+fabsf(g3.z-t3.z)+fabsf(g3.w-t3.w);
    return a;
}

// =============================================================================
__global__ void __launch_bounds__(256, 5)
K(const float* __restrict__ sem, const int* __restrict__ cl,
  const float* __restrict__ geo, const float* __restrict__ gd,
  const float* __restrict__ gg,  const float* __restrict__ gr,
  const int*   __restrict__ lbl, const float* __restrict__ emb,
  float* __restrict__ out, int out_size)
{
    int bid = blockIdx.x;

    // ======================= SEG =============================================
    if (bid < SEG_BLOCKS) {
        int b   = bid / SEG_BLK_PER_IMG;
        int blk = bid - b*SEG_BLK_PER_IMG;

        __shared__ float s_cnt[NINST], s_ws[NINST], s_ew[NINST*EDIM];
        for (int i = threadIdx.x; i < NINST; i += blockDim.x) { s_cnt[i]=0.f; s_ws[i]=0.f; }
        for (int i = threadIdx.x; i < NINST*EDIM; i += blockDim.x) s_ew[i]=0.f;
        __syncthreads();

        const int*   L = lbl + b*HW;
        const float* E = emb + (size_t)b*EDIM*HW;

        int r = blk*blockDim.x + threadIdx.x;
        int y  = r / RUNS_X;
        int x0 = (r - y*RUNS_X) * 16;
        int base = y*Wn + x0;

        const int*  rM = L + base;
        const int4* m4 = (const int4*)rM;
        int4 a0 = m4[0], a1 = m4[1], a2 = m4[2], a3 = m4[3];
        int l = a0.x;
        bool uni = (a0.y==l)&(a0.z==l)&(a0.w==l)
                 & (a1.x==l)&(a1.y==l)&(a1.z==l)&(a1.w==l)
                 & (a2.x==l)&(a2.y==l)&(a2.z==l)&(a2.w==l)
                 & (a3.x==l)&(a3.y==l)&(a3.z==l)&(a3.w==l);

        if (uni) {
            int ym = y > 0 ? y-1 : 0, yp = y < Hn-1 ? y+1 : Hn-1;
            const int* rT = L + ym*Wn + x0;
            const int* rB = L + yp*Wn + x0;
            const int4* t4 = (const int4*)rT;
            const int4* b4 = (const int4*)rB;
            unsigned int bad = 0;
            #pragma unroll
            for (int k = 0; k < 4; k++) {
                int4 tt = t4[k];
                bad |= ((unsigned)(tt.x!=l)<<(1+4*k)) | ((unsigned)(tt.y!=l)<<(2+4*k))
                     | ((unsigned)(tt.z!=l)<<(3+4*k)) | ((unsigned)(tt.w!=l)<<(4+4*k));
                int4 bb = b4[k];
                bad |= ((unsigned)(bb.x!=l)<<(1+4*k)) | ((unsigned)(bb.y!=l)<<(2+4*k))
                     | ((unsigned)(bb.z!=l)<<(3+4*k)) | ((unsigned)(bb.w!=l)<<(4+4*k));
            }
            int xl = (x0 > 0) ? -1 : 0;
            int xr = (x0+16 < Wn) ? 16 : 15;
            bad |= (unsigned)(rT[xl]!=l) | ((unsigned)(rT[xr]!=l)<<17);
            bad |= (unsigned)(rB[xl]!=l) | ((unsigned)(rB[xr]!=l)<<17);
            bad |= (unsigned)(rM[xl]!=l) | ((unsigned)(rM[xr]!=l)<<17);

            unsigned int mask = (bad | (bad>>1) | (bad>>2)) & 0xFFFFu;

            atomicAdd(&s_cnt[l], 16.0f);
            atomicAdd(&s_ws [l], 16.0f + 9.0f*(float)__popc(mask));
            #pragma unroll
            for (int c = 0; c < EDIM; c++) {
                const float4* Ep = (const float4*)(E + (size_t)c*HW + base);
                float4 e0 = Ep[0], e1 = Ep[1], e2 = Ep[2], e3 = Ep[3];
                float ev[16] = {e0.x,e0.y,e0.z,e0.w, e1.x,e1.y,e1.z,e1.w,
                                e2.x,e2.y,e2.z,e2.w, e3.x,e3.y,e3.z,e3.w};
                float acc = 0.f;
                #pragma unroll
                for (int i = 0; i < 16; i++)
                    acc += ev[i] * fmaf((float)((mask>>i)&1u), 9.0f, 1.0f);
                atomicAdd(&s_ew[l*EDIM+c], acc);
            }
            g_runinfo[b*RUNS_PER_IMG + r] = mask | ((unsigned)l<<16) | (1u<<31);
        } else {
            int ls[16] = {a0.x,a0.y,a0.z,a0.w, a1.x,a1.y,a1.z,a1.w,
                          a2.x,a2.y,a2.z,a2.w, a3.x,a3.y,a3.z,a3.w};
            unsigned int mask = 0;
            #pragma unroll 1
            for (int i = 0; i < 16; i++) {
                int li = ls[i];
                float w = bweight(L, y, x0+i, li);
                if (w > 1.f) mask |= (1u<<i);
                atomicAdd(&s_cnt[li], 1.0f);
                atomicAdd(&s_ws [li], w);
                for (int c = 0; c < EDIM; c++)
                    atomicAdd(&s_ew[li*EDIM+c], E[(size_t)c*HW + base + i] * w);
            }
            g_runinfo[b*RUNS_PER_IMG + r] = mask;
        }
        __syncthreads();
        for (int i = threadIdx.x; i < NINST; i += blockDim.x) {
            if (s_cnt[i] != 0.f) atomicAdd(&g_s.cnt[b*NINST+i], s_cnt[i]);
            if (s_ws [i] != 0.f) atomicAdd(&g_s.ws [b*NINST+i], s_ws [i]);
        }
        for (int i = threadIdx.x; i < NINST*EDIM; i += blockDim.x)
            if (s_ew[i] != 0.f) atomicAdd(&g_s.ew[b*NINST*EDIM+i], s_ew[i]);

        signal_done(&g_s.done_seg);
        return;
    }
    bid -= SEG_BLOCKS;

    // ======================= AFF (flat L1 stream) ============================
    if (bid < AFF_BLOCKS) {
        long c0 = (long)bid * AFF_CHUNK;          // f4 index into geo
        int  b  = (int)(c0 / F16);
        long k0 = c0 - (long)b*F16;               // f4 offset within batch's 16HW

        const float4* gsrc = (const float4*)geo + c0 + threadIdx.x;
        const float4* tsrc;
        double* dst;
        if (k0 < F9) {
            tsrc = (const float4*)gd + (long)b*F9 + k0;
            dst = &g_s.a9;
        } else if (k0 < F9 + F3) {
            tsrc = (const float4*)gg + (long)b*F3 + (k0 - F9);
            dst = &g_s.a3;
        } else {
            tsrc = (const float4*)gr + (long)b*F4q + (k0 - F9 - F3);
            dst = &g_s.a4;
        }
        tsrc += threadIdx.x;

        float acc = l1_4(gsrc, tsrc) + l1_4(gsrc + 1024, tsrc + 1024);
        block_acc(acc, dst);
        signal_done(&g_s.done_sem);
        return;
    }
    bid -= AFF_BLOCKS;

    // ======================= SEMPX (log-softmax NLL) =========================
    if (bid < SEMPX_BLOCKS) {
        int t  = bid*blockDim.x + threadIdx.x;
        int H4 = HW/4;
        int b  = t / H4;
        int q4 = t - b*H4;
        size_t q = (size_t)q4 * 4;

        const float4* s4 = (const float4*)(sem + (size_t)b*NCLS*HW + q);
        float4 x0 = __ldcs(s4);
        float4 x1 = __ldcs(s4 + HW/4);
        float4 x2 = __ldcs(s4 + 2*(HW/4));
        float4 x3 = __ldcs(s4 + 3*(HW/4));
        int4 cc = __ldcs((const int4*)(cl + (size_t)b*HW + q));

        float s = 0.f;
        {
            float a[4][4] = {{x0.x,x1.x,x2.x,x3.x},{x0.y,x1.y,x2.y,x3.y},
                             {x0.z,x1.z,x2.z,x3.z},{x0.w,x1.w,x2.w,x3.w}};
            int   ci[4] = {cc.x, cc.y, cc.z, cc.w};
            #pragma unroll
            for (int j = 0; j < 4; j++) {
                float m = fmaxf(fmaxf(a[j][0],a[j][1]), fmaxf(a[j][2],a[j][3]));
                float sum = __expf(a[j][0]-m)+__expf(a[j][1]-m)
                          + __expf(a[j][2]-m)+__expf(a[j][3]-m);
                float lse = m + __logf(sum);
                int c = ci[j];
                float xc = (c==0) ? a[j][0] : ((c==1) ? a[j][1] : ((c==2) ? a[j][2] : a[j][3]));
                s += lse - xc;
            }
        }
        block_acc(s, &g_s.sem);
        signal_done(&g_s.done_sem);
        return;
    }
    bid -= SEMPX_BLOCKS;

    // ======================= PULL (waits on seg) =============================
    if (bid < K2_BLOCKS) {
        spin_until(&g_s.done_seg, SEG_BLOCKS);

        int b   = bid / K2_BLK_PER_IMG;
        int blk = bid - b*K2_BLK_PER_IMG;

        __shared__ float s_ctr[NINST*EDIM];
        __shared__ float s_pull[NINST];
        for (int i = threadIdx.x; i < NINST*EDIM; i += blockDim.x)
            s_ctr[i] = g_s.ew[b*NINST*EDIM + i] / (g_s.ws[b*NINST + (i>>3)] + 1e-8f);
        for (int i = threadIdx.x; i < NINST; i += blockDim.x) s_pull[i] = 0.f;
        __syncthreads();

        const float* E = emb + (size_t)b*EDIM*HW;

        int r8 = blk*blockDim.x + threadIdx.x;
        int y  = r8 / (2*RUNS_X);
        int x8 = (r8 - y*(2*RUNS_X)) * 8;
        int base = y*Wn + x8;

        unsigned int info = g_runinfo[b*RUNS_PER_IMG + y*RUNS_X + (x8>>4)];
        unsigned int mask8 = (info >> (((x8>>3)&1)*8)) & 0xFFu;

        if (info & (1u<<31)) {
            int l = (int)((info>>16) & 0x3Fu);
            float ss[8];
            #pragma unroll
            for (int i = 0; i < 8; i++) ss[i] = 0.f;
            #pragma unroll
            for (int c = 0; c < EDIM; c++) {
                float ccv = s_ctr[l*EDIM+c];
                const float4* Ep = (const float4*)(E + (size_t)c*HW + base);
                float4 e0 = Ep[0], e1 = Ep[1];
                float d0=e0.x-ccv, d1=e0.y-ccv, d2=e0.z-ccv, d3=e0.w-ccv;
                float d4=e1.x-ccv, d5=e1.y-ccv, d6=e1.z-ccv, d7=e1.w-ccv;
                ss[0]+=d0*d0; ss[1]+=d1*d1; ss[2]+=d2*d2; ss[3]+=d3*d3;
                ss[4]+=d4*d4; ss[5]+=d5*d5; ss[6]+=d6*d6; ss[7]+=d7*d7;
            }
            float acc = 0.f;
            #pragma unroll
            for (int i = 0; i < 8; i++) {
                float dist = sqrtf(fmaxf(ss[i], 1e-12f));
                float t = fmaxf(dist - 0.5f, 0.f);
                float w = fmaf((float)((mask8>>i)&1u), 9.0f, 1.0f);
                acc += t*t*w;
            }
            atomicAdd(&s_pull[l], acc);
        } else {
            const int* Lp = lbl + b*HW + base;
            int4 L0 = ((const int4*)Lp)[0];
            int4 L1 = ((const int4*)Lp)[1];
            int ls[8] = {L0.x,L0.y,L0.z,L0.w, L1.x,L1.y,L1.z,L1.w};
            #pragma unroll 1
            for (int i = 0; i < 8; i++) {
                int l = ls[i];
                float ssv = 0.f;
                for (int c = 0; c < EDIM; c++) {
                    float d = E[(size_t)c*HW + base + i] - s_ctr[l*EDIM+c];
                    ssv += d*d;
                }
                float dist = sqrtf(fmaxf(ssv, 1e-12f));
                float t = fmaxf(dist - 0.5f, 0.f);
                float w = fmaf((float)((mask8>>i)&1u), 9.0f, 1.0f);
                atomicAdd(&s_pull[l], t*t*w);
            }
        }
        __syncthreads();
        for (int i = threadIdx.x; i < NINST; i += blockDim.x)
            if (s_pull[i] != 0.f) atomicAdd(&g_s.pull[b*NINST+i], s_pull[i]);

        signal_done(&g_s.done_k2);
        return;
    }

    // ======================= FINALIZE ========================================
    spin_until(&g_s.done_sem, DONE_SEM_TARGET);
    spin_until(&g_s.done_k2,  K2_BLOCKS);

    __shared__ float s_ctr[Bn][NINST*EDIM];
    __shared__ float s_cnt[Bn][NINST];
    __shared__ float rp[Bn], rq[Bn], rn[Bn];
    __shared__ int   rpres[Bn];

    for (int i = threadIdx.x; i < Bn*NINST*EDIM; i += blockDim.x) {
        int b = i / (NINST*EDIM), k = i % (NINST*EDIM);
        s_ctr[b][k] = g_s.ew[i] / (g_s.ws[b*NINST + (k>>3)] + 1e-8f);
    }
    for (int i = threadIdx.x; i < Bn*NINST; i += blockDim.x)
        s_cnt[i/NINST][i%NINST] = g_s.cnt[i];
    __syncthreads();

    int wid = threadIdx.x >> 5, lane = threadIdx.x & 31;
    if (wid < Bn) {
        int b = wid;
        float pull = 0, norm = 0; int np = 0;
        for (int k = lane; k < NINST; k += 32) {
            bool pres = (k > 0) && (s_cnt[b][k] > 0.f);
            if (pres) {
                pull += g_s.pull[b*NINST+k] / fmaxf(s_cnt[b][k], 1.0f);
                float ssn = 0;
                #pragma unroll
                for (int c = 0; c < EDIM; c++) { float v = s_ctr[b][k*EDIM+c]; ssn += v*v; }
                norm += sqrtf(fmaxf(ssn, 1e-12f));
                np++;
            }
        }
        float push = 0; int npair = 0;
        for (int idx = lane; idx < NINST*NINST; idx += 32) {
            int i = idx / NINST, j = idx % NINST;
            if (j > i && i > 0 && s_cnt[b][i] > 0.f && s_cnt[b][j] > 0.f) {
                float ssd = 0;
                #pragma unroll
                for (int c = 0; c < EDIM; c++) {
                    float d = s_ctr[b][i*EDIM+c] - s_ctr[b][j*EDIM+c];
                    ssd += d*d;
                }
                float pd = sqrtf(fmaxf(ssd, 1e-12f));
                float t = fmaxf(3.0f - pd, 0.f);
                push += t*t; npair++;
            }
        }
        pull = warp_redf(pull); norm = warp_redf(norm); push = warp_redf(push);
        np   = __reduce_add_sync(0xffffffffu, np);
        npair= __reduce_add_sync(0xffffffffu, npair);
        if (lane == 0) {
            rp[b] = pull;
            rq[b] = push / fmaxf((float)npair, 1.0f);
            rn[b] = norm / fmaxf((float)np, 1.0f);
            rpres[b] = (np > 0) ? 1 : 0;
        }
    }
    __syncthreads();
    if (threadIdx.x == 0) {
        float pull = 0, push = 0, norm = 0; int n = 0;
        for (int bb = 0; bb < Bn; bb++) { pull += rp[bb]; push += rq[bb]; norm += rn[bb]; n += rpres[bb]; }
        float nn  = fmaxf((float)n, 1.0f);
        float ins = (pull + push + 0.001f*norm) / nn;
        float semv = (float)(g_s.sem / (double)NPIX);
        float aff  = (float)(g_s.a9/(double)((size_t)Bn*9*HW)
                           + g_s.a3/(double)((size_t)Bn*3*HW)
                           + g_s.a4/(double)((size_t)Bn*4*HW));
        out[0] = semv + aff + ins;
        if (out_size > 1) out[1] = semv;
        if (out_size > 2) out[2] = aff;
        if (out_size > 3) out[3] = ins;
    }
}

// ---------------- entry -------------------------------------------------------
extern "C" void kernel_launch(void* const* d_in, const int* in_sizes, int n_in,
                              void* d_out, int out_size)
{
    const float* sem  = (const float*)d_in[0];
    const int*   cl   = (const int*)  d_in[1];
    const float* inst = (const float*)d_in[2];
    const float* geo  = (const float*)d_in[3];
    const float* gd   = (const float*)d_in[4];
    const float* gg   = (const float*)d_in[5];
    const float* gr   = (const float*)d_in[6];
    const int*   lbl  = (const int*)  d_in[7];
    float* out = (float*)d_out;

    void* scr = nullptr;
    cudaGetSymbolAddress(&scr, g_s);
    cudaMemsetAsync(scr, 0, sizeof(Scr));

    K<<<TOTAL_BLOCKS, 256>>>(sem, cl, geo, gd, gg, gr, lbl, inst, out, out_size);
}